// round 3
// baseline (speedup 1.0000x reference)
#include <cuda_runtime.h>
#include <stdint.h>

// ScaledNeuron: IF neuron, soft reset, V_TH=1.0, SCALE=1.0, v0=0.5.
// xs: [B=16, C=64, H=64, W=64, T=8] fp32, T contiguous.
// For each spatial location (4,194,304 of them):
//   v = 0.5
//   for t in 0..7:  v += x[t]; s = (v >= 1.0f); v -= s; out[t] = s;
//
// Pure HBM stream: 2 x float4 load + 2 x float4 store per thread.

static constexpr int T = 8;
static constexpr long long N_LOC = 16LL * 64 * 64 * 64;  // 4,194,304

__global__ __launch_bounds__(256)
void scaled_neuron_kernel(const float4* __restrict__ in,
                          float4* __restrict__ out,
                          int n_loc) {
    int i = blockIdx.x * blockDim.x + threadIdx.x;
    if (i >= n_loc) return;

    // Each location = 8 contiguous floats = 2 float4, 32B-aligned.
    float4 a = in[2 * i];
    float4 b = in[2 * i + 1];

    float v = 0.5f;
    float x[T] = {a.x, a.y, a.z, a.w, b.x, b.y, b.z, b.w};
    float s[T];

#pragma unroll
    for (int t = 0; t < T; t++) {
        v += x[t];
        float sp = (v >= 1.0f) ? 1.0f : 0.0f;  // Heaviside(v - V_TH)
        v -= sp;                                // soft reset
        s[t] = sp;                              // * SCALE (=1.0)
    }

    float4 oa = make_float4(s[0], s[1], s[2], s[3]);
    float4 ob = make_float4(s[4], s[5], s[6], s[7]);
    out[2 * i]     = oa;
    out[2 * i + 1] = ob;
}

extern "C" void kernel_launch(void* const* d_in, const int* in_sizes, int n_in,
                              void* d_out, int out_size) {
    const float4* in = (const float4*)d_in[0];
    float4* out = (float4*)d_out;

    int n_loc = in_sizes[0] / T;  // total elements / T = spatial locations
    int threads = 256;
    int blocks = (n_loc + threads - 1) / threads;

    scaled_neuron_kernel<<<blocks, threads>>>(in, out, n_loc);
}